// round 2
// baseline (speedup 1.0000x reference)
#include <cuda_runtime.h>
#include <math.h>

#define Bsz  16
#define Nseq 512
#define Dd   256
#define DIm  512
#define Ssz  16
#define Rsz  16
#define Hh   512
#define Ee   10
#define Kc   3
#define Pp   96
#define ROWS (Bsz*Nseq)   /* 8192 */

// ---------------- scratch (static device globals; no allocs) ----------------
__device__ float g_x  [ROWS*Dd];
__device__ float g_xn [ROWS*Dd];
__device__ float g_xiz[(size_t)ROWS*2*DIm];
__device__ float g_xc [(size_t)ROWS*DIm];
__device__ float g_dbc[ROWS*48];
__device__ float g_dt [(size_t)ROWS*DIm];
__device__ float g_y  [(size_t)ROWS*DIm];
__device__ float g_t1 [ROWS*Dd];
__device__ float g_t2 [ROWS*Dd];
__device__ float g_sup[Nseq*Nseq];
__device__ float g_wn [(size_t)Nseq*Kc*Dd*Dd];   // 403 MB
__device__ float g_x2 [ROWS*Dd];

// ---------------- generic fp32 GEMM: C[=|+=] act(A@B + bias) ----------------
// A: M x K (row major), B: K x N, C: M x N. Optional per-(N/period)-block row
// flip on A reads / C writes (handles jnp.flip of the sequence axis).
// blockIdx.z batches with strides (elements).
#define BM 64
#define BN 64
#define BK 16

__global__ void gemm_kernel(const float* __restrict__ A, const float* __restrict__ Bm,
                            const float* __restrict__ bias, float* __restrict__ C,
                            int M, int Kd, int Nd,
                            int flipA, int flipC, int period,
                            int accumulate, int act,
                            long sA, long sB, long sC)
{
    A  += (long)blockIdx.z * sA;
    Bm += (long)blockIdx.z * sB;
    C  += (long)blockIdx.z * sC;

    __shared__ float As[BK][BM];
    __shared__ float Bs[BK][BN];

    int tid  = threadIdx.x;           // 256 threads
    int brow = blockIdx.y * BM;
    int bcol = blockIdx.x * BN;
    int tr   = (tid / 16) * 4;
    int tc   = (tid % 16) * 4;

    float acc[4][4];
#pragma unroll
    for (int i = 0; i < 4; i++)
#pragma unroll
        for (int j = 0; j < 4; j++) acc[i][j] = 0.f;

    for (int k0 = 0; k0 < Kd; k0 += BK) {
#pragma unroll
        for (int i = 0; i < 4; i++) {
            int idx = tid + i * 256;
            // A tile: 64 rows x 16 cols
            int r  = idx >> 4, c = idx & 15;
            int gr = brow + r, gc = k0 + c;
            float v = 0.f;
            if (gr < M && gc < Kd) {
                int pr = gr;
                if (flipA) { int q = gr / period, rm = gr - q * period; pr = q * period + (period - 1 - rm); }
                v = A[(long)pr * Kd + gc];
            }
            As[c][r] = v;
            // B tile: 16 rows x 64 cols
            int r2 = idx >> 6, c2 = idx & 63;
            int gr2 = k0 + r2, gc2 = bcol + c2;
            float v2 = 0.f;
            if (gr2 < Kd && gc2 < Nd) v2 = Bm[(long)gr2 * Nd + gc2];
            Bs[r2][c2] = v2;
        }
        __syncthreads();
#pragma unroll
        for (int kk = 0; kk < BK; kk++) {
            float a[4], b[4];
#pragma unroll
            for (int i = 0; i < 4; i++) a[i] = As[kk][tr + i];
#pragma unroll
            for (int j = 0; j < 4; j++) b[j] = Bs[kk][tc + j];
#pragma unroll
            for (int i = 0; i < 4; i++)
#pragma unroll
                for (int j = 0; j < 4; j++) acc[i][j] = fmaf(a[i], b[j], acc[i][j]);
        }
        __syncthreads();
    }

#pragma unroll
    for (int i = 0; i < 4; i++) {
        int gr = brow + tr + i;
        if (gr >= M) continue;
        int pr = gr;
        if (flipC) { int q = gr / period, rm = gr - q * period; pr = q * period + (period - 1 - rm); }
#pragma unroll
        for (int j = 0; j < 4; j++) {
            int gc = bcol + tc + j;
            if (gc >= Nd) continue;
            float v = acc[i][j];
            if (bias) v += bias[gc];
            if (act == 1) v = v / (1.f + __expf(-v));   // silu
            long off = (long)pr * Nd + gc;
            if (accumulate) C[off] += v; else C[off] = v;
        }
    }
}

// ---------------- layernorm over D=256 (one block per row) ----------------
__global__ void ln_kernel(const float* __restrict__ x, const float* __restrict__ g,
                          const float* __restrict__ b, float* __restrict__ out)
{
    int row = blockIdx.x;
    int d   = threadIdx.x;    // 256 == Dd
    float v = x[(long)row * Dd + d];
    float s1 = v, s2 = v * v;
#pragma unroll
    for (int o = 16; o > 0; o >>= 1) {
        s1 += __shfl_xor_sync(0xffffffffu, s1, o);
        s2 += __shfl_xor_sync(0xffffffffu, s2, o);
    }
    __shared__ float a1[8], a2[8];
    __shared__ float mean, rstd;
    if ((d & 31) == 0) { a1[d >> 5] = s1; a2[d >> 5] = s2; }
    __syncthreads();
    if (d == 0) {
        float t1 = 0.f, t2 = 0.f;
        for (int i = 0; i < 8; i++) { t1 += a1[i]; t2 += a2[i]; }
        float m = t1 / (float)Dd;
        float var = t2 / (float)Dd - m * m;
        mean = m;
        rstd = rsqrtf(var + 1e-5f);
    }
    __syncthreads();
    out[(long)row * Dd + d] = (v - mean) * rstd * g[d] + b[d];
}

// -------- causal depthwise conv (width 4) + silu.  xi = g_xiz[:, :DIm] --------
__global__ void conv_silu_kernel(const float* __restrict__ xiz, const float* __restrict__ cw,
                                 const float* __restrict__ cb, float* __restrict__ xc)
{
    int d   = blockIdx.x * 128 + threadIdx.x;  // 0..511
    int row = blockIdx.y;                      // b*Nseq + l
    int b   = row >> 9;
    int l   = row & (Nseq - 1);
    float v = cb[d];
#pragma unroll
    for (int j = 0; j < 4; j++) {
        int l2 = l + j - 3;
        if (l2 >= 0) v = fmaf(xiz[((long)(b * Nseq + l2)) * (2 * DIm) + d], cw[d * 4 + j], v);
    }
    xc[(long)row * DIm + d] = v / (1.f + __expf(-v));
}

// -------- dt = softplus(dbc[:, :16] @ W_dt + b_dt) --------
__global__ void dt_kernel(const float* __restrict__ dbc, const float* __restrict__ Wd,
                          const float* __restrict__ bd, float* __restrict__ dt)
{
    int row = blockIdx.y;
    int d   = blockIdx.x * 128 + threadIdx.x;
    __shared__ float s[16];
    if (threadIdx.x < 16) s[threadIdx.x] = dbc[(long)row * 48 + threadIdx.x];
    __syncthreads();
    float v = bd[d];
#pragma unroll
    for (int r = 0; r < Rsz; r++) v = fmaf(s[r], Wd[r * DIm + d], v);
    dt[(long)row * DIm + d] = (v > 20.f) ? v : log1pf(__expf(v));
}

// -------- SSM scan: half-warp per (b,d) channel; lane%16 = state s --------
// y[b,l,d] = (sum_s h_s * C_s + xc*Dp) * silu(z)
__global__ void scan_kernel(const float* __restrict__ dtb, const float* __restrict__ xc,
                            const float* __restrict__ dbc, const float* __restrict__ xiz,
                            const float* __restrict__ A_log, const float* __restrict__ Dsk,
                            float* __restrict__ y)
{
    int tid  = threadIdx.x;      // 256 = 8 warps = 16 scans
    int warp = tid >> 5, lane = tid & 31;
    int half = lane >> 4, s = lane & 15;
    int id = blockIdx.x * 16 + warp * 2 + half;   // [0, Bsz*DIm)
    int b  = id >> 9;            // / DIm
    int d  = id & (DIm - 1);

    float negA = -__expf(A_log[d * Ssz + s]);
    float Dp   = Dsk[d];
    float h    = 0.f;

    for (int l = 0; l < Nseq; l++) {
        long row = (long)b * Nseq + l;
        float dtv = dtb[row * DIm + d];
        float xcv = xc [row * DIm + d];
        float Bmv = dbc[row * 48 + Rsz + s];
        float Cmv = dbc[row * 48 + Rsz + Ssz + s];
        h = fmaf(__expf(dtv * negA), h, dtv * xcv * Bmv);
        float p = h * Cmv;
        p += __shfl_xor_sync(0xffffffffu, p, 1);
        p += __shfl_xor_sync(0xffffffffu, p, 2);
        p += __shfl_xor_sync(0xffffffffu, p, 4);
        p += __shfl_xor_sync(0xffffffffu, p, 8);
        if (s == 0) {
            float z = xiz[row * (2 * DIm) + DIm + d];
            y[row * DIm + d] = (p + xcv * Dp) * (z / (1.f + __expf(-z)));
        }
    }
}

// -------- sup = softmax_row(relu(emb @ emb^T)) --------
__global__ void sup_kernel(const float* __restrict__ emb, float* __restrict__ sup)
{
    int n   = blockIdx.x;
    int tid = threadIdx.x;   // 256; each handles m = tid, tid+256
    __shared__ float en[16];
    __shared__ float red[8];
    __shared__ float smx, ssum;
    if (tid < Ee) en[tid] = emb[n * Ee + tid];
    __syncthreads();
    float v0 = 0.f, v1 = 0.f;
#pragma unroll
    for (int e = 0; e < Ee; e++) {
        float ee = en[e];
        v0 = fmaf(ee, emb[tid * Ee + e], v0);
        v1 = fmaf(ee, emb[(tid + 256) * Ee + e], v1);
    }
    float sc0 = fmaxf(v0, 0.f), sc1 = fmaxf(v1, 0.f);
    float mx = fmaxf(sc0, sc1);
#pragma unroll
    for (int o = 16; o > 0; o >>= 1) mx = fmaxf(mx, __shfl_xor_sync(0xffffffffu, mx, o));
    if ((tid & 31) == 0) red[tid >> 5] = mx;
    __syncthreads();
    if (tid == 0) {
        float v = red[0];
        for (int i = 1; i < 8; i++) v = fmaxf(v, red[i]);
        smx = v;
    }
    __syncthreads();
    float e0 = __expf(sc0 - smx), e1 = __expf(sc1 - smx);
    float sl = e0 + e1;
#pragma unroll
    for (int o = 16; o > 0; o >>= 1) sl += __shfl_xor_sync(0xffffffffu, sl, o);
    __syncthreads();     // protect red[] reuse
    if ((tid & 31) == 0) red[tid >> 5] = sl;
    __syncthreads();
    if (tid == 0) {
        float v = 0.f;
        for (int i = 0; i < 8; i++) v += red[i];
        ssum = v;
    }
    __syncthreads();
    float inv = 1.f / ssum;
    sup[n * Nseq + tid]       = e0 * inv;
    sup[n * Nseq + tid + 256] = e1 * inv;
}

// -------- Wn[n,k,d,o] = sum_e emb[n,e] * pool[e,k,d,o] --------
__global__ void wn_kernel(const float* __restrict__ pool, const float* __restrict__ emb,
                          float* __restrict__ wn)
{
    int kd = blockIdx.x;    // 0..767  (k*256 + d)
    int o  = threadIdx.x;   // 0..255
    float pe[Ee];
#pragma unroll
    for (int e = 0; e < Ee; e++) pe[e] = pool[((long)e * (Kc * Dd) + kd) * Dd + o];
    for (int n = 0; n < Nseq; n++) {
        float w = 0.f;
#pragma unroll
        for (int e = 0; e < Ee; e++) w = fmaf(__ldg(&emb[n * Ee + e]), pe[e], w);
        wn[((long)n * (Kc * Dd) + kd) * Dd + o] = w;
    }
}

// -------- x2[b,n,o] = sum_{k,d} xg[b,k,n,d]*Wn[n,k,d,o] + (emb@bias_pool)[n,o]
// xg0=x, xg1=t1=sup@x, xg2=2*t2-x, t2=sup@t1. One block per n, all 16 b in smem.
__global__ void x2_kernel(const float* __restrict__ x, const float* __restrict__ t1,
                          const float* __restrict__ t2, const float* __restrict__ wn,
                          const float* __restrict__ emb, const float* __restrict__ bpool,
                          float* __restrict__ x2)
{
    int n = blockIdx.x;
    int o = threadIdx.x;  // 256
    __shared__ float xs[Kc][Bsz][Dd];
    for (int b = 0; b < Bsz; b++) {
        long off = ((long)b * Nseq + n) * Dd + o;
        float xv = x[off];
        xs[0][b][o] = xv;
        xs[1][b][o] = t1[off];
        xs[2][b][o] = 2.f * t2[off] - xv;
    }
    __syncthreads();
    float acc[Bsz];
#pragma unroll
    for (int b = 0; b < Bsz; b++) acc[b] = 0.f;
    const float* wp = wn + (long)n * (Kc * Dd) * Dd;
    for (int kd = 0; kd < Kc * Dd; kd++) {
        float w = wp[(long)kd * Dd + o];
        int k = kd >> 8, d = kd & 255;
#pragma unroll
        for (int b = 0; b < Bsz; b++) acc[b] = fmaf(xs[k][b][d], w, acc[b]);
    }
    float bias = 0.f;
#pragma unroll
    for (int e = 0; e < Ee; e++) bias = fmaf(emb[n * Ee + e], bpool[e * Dd + o], bias);
    for (int b = 0; b < Bsz; b++)
        x2[((long)b * Nseq + n) * Dd + o] = acc[b] + bias;
}

// ---------------- host-side orchestration ----------------
static inline void gemm(const float* A, const float* B, const float* bias, float* C,
                        int M, int K, int N, int flipA, int flipC,
                        int accumulate, int act,
                        int batch = 1, long sA = 0, long sB = 0, long sC = 0)
{
    dim3 grid((N + BN - 1) / BN, (M + BM - 1) / BM, batch);
    gemm_kernel<<<grid, 256>>>(A, B, bias, C, M, K, N, flipA, flipC, Nseq,
                               accumulate, act, sA, sB, sC);
}

extern "C" void kernel_launch(void* const* d_in, const int* in_sizes, int n_in,
                              void* d_out, int out_size)
{
    const float* input_  = (const float*)d_in[0];
    const float* ln1_g   = (const float*)d_in[1];
    const float* ln1_b   = (const float*)d_in[2];
    const float* ln2_g   = (const float*)d_in[3];
    const float* ln2_b   = (const float*)d_in[4];
    const float* W_in    = (const float*)d_in[5];
    const float* conv_w  = (const float*)d_in[6];
    const float* conv_b  = (const float*)d_in[7];
    const float* W_xproj = (const float*)d_in[8];
    const float* W_dt    = (const float*)d_in[9];
    const float* b_dt    = (const float*)d_in[10];
    const float* A_log   = (const float*)d_in[11];
    const float* D_skip  = (const float*)d_in[12];
    const float* W_out   = (const float*)d_in[13];
    const float* ffn_W1  = (const float*)d_in[14];
    const float* ffn_b1  = (const float*)d_in[15];
    const float* ffn_W2  = (const float*)d_in[16];
    const float* ffn_b2  = (const float*)d_in[17];
    const float* node_emb     = (const float*)d_in[18];
    const float* weights_pool = (const float*)d_in[19];
    const float* bias_pool    = (const float*)d_in[20];
    const float* W_proj  = (const float*)d_in[21];
    const float* b_proj  = (const float*)d_in[22];
    float* out = (float*)d_out;

    float *x_, *xn_, *xiz_, *xc_, *dbc_, *dt_, *y_, *t1_, *t2_, *sup_, *wn_, *x2_;
    cudaGetSymbolAddress((void**)&x_,   g_x);
    cudaGetSymbolAddress((void**)&xn_,  g_xn);
    cudaGetSymbolAddress((void**)&xiz_, g_xiz);
    cudaGetSymbolAddress((void**)&xc_,  g_xc);
    cudaGetSymbolAddress((void**)&dbc_, g_dbc);
    cudaGetSymbolAddress((void**)&dt_,  g_dt);
    cudaGetSymbolAddress((void**)&y_,   g_y);
    cudaGetSymbolAddress((void**)&t1_,  g_t1);
    cudaGetSymbolAddress((void**)&t2_,  g_t2);
    cudaGetSymbolAddress((void**)&sup_, g_sup);
    cudaGetSymbolAddress((void**)&wn_,  g_wn);
    cudaGetSymbolAddress((void**)&x2_,  g_x2);

    // x = input
    cudaMemcpyAsync(x_, input_, (size_t)ROWS * Dd * sizeof(float),
                    cudaMemcpyDeviceToDevice);

    for (int layer = 0; layer < 3; layer++) {
        // xn = LN1(x)
        ln_kernel<<<ROWS, Dd>>>(x_, ln1_g, ln1_b, xn_);

        for (int dir = 0; dir < 2; dir++) {
            const float* Wi = W_in    + (long)dir * Dd * 2 * DIm;
            const float* cw = conv_w  + (long)dir * DIm * 4;
            const float* cb = conv_b  + (long)dir * DIm;
            const float* Wx = W_xproj + (long)dir * DIm * (Rsz + 2 * Ssz);
            const float* Wd = W_dt    + (long)dir * Rsz * DIm;
            const float* bd = b_dt    + (long)dir * DIm;
            const float* Al = A_log   + (long)dir * DIm * Ssz;
            const float* Dp = D_skip  + (long)dir * DIm;
            const float* Wo = W_out   + (long)dir * DIm * Dd;

            // xiz = (dir ? flip(xn) : xn) @ Wi
            gemm(xn_, Wi, nullptr, xiz_, ROWS, Dd, 2 * DIm, dir, 0, 0, 0);
            // xc = silu(causal_conv(xi))
            conv_silu_kernel<<<dim3(DIm / 128, ROWS), 128>>>(xiz_, cw, cb, xc_);
            // dbc = xc @ Wx   (48 cols: dt_in | B | C)
            gemm(xc_, Wx, nullptr, dbc_, ROWS, DIm, Rsz + 2 * Ssz, 0, 0, 0, 0);
            // dt = softplus(dbc[:, :16] @ Wd + bd)
            dt_kernel<<<dim3(DIm / 128, ROWS), 128>>>(dbc_, Wd, bd, dt_);
            // selective scan -> y (includes D_skip and *silu(z))
            scan_kernel<<<(Bsz * DIm) / 16, 256>>>(dt_, xc_, dbc_, xiz_, Al, Dp, y_);
            // x += (flip back if dir) y @ Wo
            gemm(y_, Wo, nullptr, x_, ROWS, DIm, Dd, 0, dir, 1, 0);
        }

        // FFN: x += silu(LN2(x) @ W1 + b1) @ W2 + b2
        ln_kernel<<<ROWS, Dd>>>(x_, ln2_g, ln2_b, xn_);
        gemm(xn_, ffn_W1, ffn_b1, xc_, ROWS, Dd, Hh, 0, 0, 0, 1);      // hidden in xc
        gemm(xc_, ffn_W2, ffn_b2, x_, ROWS, Hh, Dd, 0, 0, 1, 0);
    }

    // graph tail
    sup_kernel<<<Nseq, 256>>>(node_emb, sup_);
    // t1[b] = sup @ x[b] ; t2[b] = sup @ t1[b]
    gemm(sup_, x_,  nullptr, t1_, Nseq, Nseq, Dd, 0, 0, 0, 0,
         Bsz, 0, (long)Nseq * Dd, (long)Nseq * Dd);
    gemm(sup_, t1_, nullptr, t2_, Nseq, Nseq, Dd, 0, 0, 0, 0,
         Bsz, 0, (long)Nseq * Dd, (long)Nseq * Dd);
    // Wn = einsum('ne,ekio->nkio')
    wn_kernel<<<Kc * Dd, Dd>>>(weights_pool, node_emb, wn_);
    // x2 = einsum('bknd,nkdo->bno') + emb@bias_pool
    x2_kernel<<<Nseq, Dd>>>(x_, t1_, t2_, wn_, node_emb, bias_pool, x2_);
    // out = x2 @ W_proj + b_proj
    gemm(x2_, W_proj, b_proj, out, ROWS, Dd, Pp, 0, 0, 0, 0);
}

// round 5
// speedup vs baseline: 1.3869x; 1.3869x over previous
#include <cuda_runtime.h>
#include <math.h>

#define Bsz  16
#define Nseq 512
#define Dd   256
#define DIm  512
#define Ssz  16
#define Rsz  16
#define Hh   512
#define Ee   10
#define Kc   3
#define Pp   96
#define ROWS (Bsz*Nseq)   /* 8192 */

// ---------------- scratch (static device globals; no allocs) ----------------
__device__ float g_x  [ROWS*Dd];
__device__ float g_xn [ROWS*Dd];
__device__ float g_xiz[(size_t)ROWS*2*DIm];
__device__ float g_xc [(size_t)ROWS*DIm];
__device__ float g_dbc[ROWS*48];
__device__ float g_dt [(size_t)ROWS*DIm];
__device__ float g_y  [(size_t)ROWS*DIm];
__device__ float g_t1 [ROWS*Dd];
__device__ float g_t2 [ROWS*Dd];
__device__ float g_sup[Nseq*Nseq];
__device__ float g_wn [(size_t)Nseq*Kc*Dd*Dd];   // 403 MB
__device__ float g_x2 [ROWS*Dd];

__device__ __forceinline__ float silu(float v) { return v / (1.f + __expf(-v)); }

// =================== 128x128x8 fp32 SGEMM, double buffered ===================
// Requires: M%128==0, N%128==0, K%8==0 (all call sites satisfy this).
// C[=|+=] act(A@B + bias); optional per-period row flip on A reads / C writes.
__global__ __launch_bounds__(256, 2)
void gemm128_kernel(const float* __restrict__ A, const float* __restrict__ Bm,
                    const float* __restrict__ bias, float* __restrict__ C,
                    int Kd, int Nd,
                    int flipA, int flipC, int period,
                    int accumulate, int act,
                    long sA, long sB, long sC)
{
    A  += (long)blockIdx.z * sA;
    Bm += (long)blockIdx.z * sB;
    C  += (long)blockIdx.z * sC;

    __shared__ float As[2][8][128];
    __shared__ float Bs[2][8][128];

    const int t    = threadIdx.x;
    const int brow = blockIdx.y * 128;
    const int bcol = blockIdx.x * 128;

    const int a_r = t >> 1, a_c = (t & 1) * 4;     // A tile load: 128x8, float4
    const int b_r = t >> 5, b_c = (t & 31) * 4;    // B tile load: 8x128, float4
    const int ty  = t >> 4, tx  = t & 15;          // compute: 16x16 threads, 8x8 frags

    int ar_g = brow + a_r;
    if (flipA) { int q = ar_g / period; ar_g = q * period + (period - 1 - (ar_g - q * period)); }
    const float* Aptr = A + (long)ar_g * Kd + a_c;
    const float* Bptr = Bm + (long)b_r * Nd + bcol + b_c;

    // prologue: tile 0
    float4 aldg = *(const float4*)Aptr;
    float4 bldg = *(const float4*)Bptr;
    As[0][a_c + 0][a_r] = aldg.x;
    As[0][a_c + 1][a_r] = aldg.y;
    As[0][a_c + 2][a_r] = aldg.z;
    As[0][a_c + 3][a_r] = aldg.w;
    *(float4*)&Bs[0][b_r][b_c] = bldg;
    __syncthreads();

    float acc[8][8];
#pragma unroll
    for (int i = 0; i < 8; i++)
#pragma unroll
        for (int j = 0; j < 8; j++) acc[i][j] = 0.f;

    const int nk = Kd >> 3;
    int buf = 0;
    for (int kt = 0; kt < nk; kt++) {
        if (kt + 1 < nk) {
            aldg = *(const float4*)(Aptr + (kt + 1) * 8);
            bldg = *(const float4*)(Bptr + (long)(kt + 1) * 8 * Nd);
        }
#pragma unroll
        for (int kk = 0; kk < 8; kk++) {
            float a[8], b[8];
            *(float4*)&a[0] = *(const float4*)&As[buf][kk][ty * 8];
            *(float4*)&a[4] = *(const float4*)&As[buf][kk][ty * 8 + 4];
            *(float4*)&b[0] = *(const float4*)&Bs[buf][kk][tx * 8];
            *(float4*)&b[4] = *(const float4*)&Bs[buf][kk][tx * 8 + 4];
#pragma unroll
            for (int i = 0; i < 8; i++)
#pragma unroll
                for (int j = 0; j < 8; j++) acc[i][j] = fmaf(a[i], b[j], acc[i][j]);
        }
        if (kt + 1 < nk) {
            int nb = buf ^ 1;
            As[nb][a_c + 0][a_r] = aldg.x;
            As[nb][a_c + 1][a_r] = aldg.y;
            As[nb][a_c + 2][a_r] = aldg.z;
            As[nb][a_c + 3][a_r] = aldg.w;
            *(float4*)&Bs[nb][b_r][b_c] = bldg;
            __syncthreads();
            buf = nb;
        }
    }

    // epilogue
#pragma unroll
    for (int i = 0; i < 8; i++) {
        int gr = brow + ty * 8 + i;
        int pr = gr;
        if (flipC) { int q = gr / period; pr = q * period + (period - 1 - (gr - q * period)); }
        float* crow = C + (long)pr * Nd + bcol + tx * 8;
#pragma unroll
        for (int j4 = 0; j4 < 2; j4++) {
            float4 v = make_float4(acc[i][j4 * 4 + 0], acc[i][j4 * 4 + 1],
                                   acc[i][j4 * 4 + 2], acc[i][j4 * 4 + 3]);
            if (bias) {
                float4 bb = *(const float4*)&bias[bcol + tx * 8 + j4 * 4];
                v.x += bb.x; v.y += bb.y; v.z += bb.z; v.w += bb.w;
            }
            if (act == 1) { v.x = silu(v.x); v.y = silu(v.y); v.z = silu(v.z); v.w = silu(v.w); }
            if (accumulate) {
                float4 o = *(const float4*)(crow + j4 * 4);
                v.x += o.x; v.y += o.y; v.z += o.z; v.w += o.w;
            }
            *(float4*)(crow + j4 * 4) = v;
        }
    }
}

// =================== skinny-N GEMM (N = NCT*16, here 48 / 96) ===================
// 64 rows per block, B panel tiled through smem. M%64==0, K%16==0 assumed.
template<int NCT>
__global__ __launch_bounds__(256)
void gemm_skinny_kernel(const float* __restrict__ A, const float* __restrict__ Bm,
                        const float* __restrict__ bias, float* __restrict__ C,
                        int Kd)
{
    const int Nd = NCT * 16;
    __shared__ float As[16][64];
    __shared__ float Bs[16][NCT * 16];

    const int t    = threadIdx.x;
    const int brow = blockIdx.x * 64;
    const int rg   = (t >> 4) * 4;   // 16 groups of 4 rows
    const int tx   = t & 15;

    const int a_r = t >> 2, a_c = (t & 3) * 4;
    const float* Aptr = A + (long)(brow + a_r) * Kd + a_c;

    float acc[4][NCT];
#pragma unroll
    for (int i = 0; i < 4; i++)
#pragma unroll
        for (int c = 0; c < NCT; c++) acc[i][c] = 0.f;

    for (int k0 = 0; k0 < Kd; k0 += 16) {
        float4 av = *(const float4*)(Aptr + k0);
        As[a_c + 0][a_r] = av.x;
        As[a_c + 1][a_r] = av.y;
        As[a_c + 2][a_r] = av.z;
        As[a_c + 3][a_r] = av.w;
        for (int idx = t; idx < 16 * Nd; idx += 256) {
            int r = idx / Nd, c = idx - r * Nd;
            Bs[r][c] = Bm[(long)(k0 + r) * Nd + c];
        }
        __syncthreads();
#pragma unroll
        for (int kk = 0; kk < 16; kk++) {
            float a[4];
            *(float4*)a = *(const float4*)&As[kk][rg];
#pragma unroll
            for (int ct = 0; ct < NCT; ct++) {
                float b = Bs[kk][ct * 16 + tx];
#pragma unroll
                for (int i = 0; i < 4; i++) acc[i][ct] = fmaf(a[i], b, acc[i][ct]);
            }
        }
        __syncthreads();
    }

#pragma unroll
    for (int i = 0; i < 4; i++) {
        int row = brow + rg + i;
#pragma unroll
        for (int ct = 0; ct < NCT; ct++) {
            int col = ct * 16 + tx;
            float v = acc[i][ct];
            if (bias) v += bias[col];
            C[(long)row * Nd + col] = v;
        }
    }
}

// ---------------- layernorm over D=256 (one block per row) ----------------
__global__ void ln_kernel(const float* __restrict__ x, const float* __restrict__ g,
                          const float* __restrict__ b, float* __restrict__ out)
{
    int row = blockIdx.x;
    int d   = threadIdx.x;    // 256 == Dd
    float v = x[(long)row * Dd + d];
    float s1 = v, s2 = v * v;
#pragma unroll
    for (int o = 16; o > 0; o >>= 1) {
        s1 += __shfl_xor_sync(0xffffffffu, s1, o);
        s2 += __shfl_xor_sync(0xffffffffu, s2, o);
    }
    __shared__ float a1[8], a2[8];
    __shared__ float mean, rstd;
    if ((d & 31) == 0) { a1[d >> 5] = s1; a2[d >> 5] = s2; }
    __syncthreads();
    if (d == 0) {
        float t1 = 0.f, t2 = 0.f;
        for (int i = 0; i < 8; i++) { t1 += a1[i]; t2 += a2[i]; }
        float m = t1 / (float)Dd;
        float var = t2 / (float)Dd - m * m;
        mean = m;
        rstd = rsqrtf(var + 1e-5f);
    }
    __syncthreads();
    out[(long)row * Dd + d] = (v - mean) * rstd * g[d] + b[d];
}

// -------- causal depthwise conv (width 4) + silu.  xi = g_xiz[:, :DIm] --------
__global__ void conv_silu_kernel(const float* __restrict__ xiz, const float* __restrict__ cw,
                                 const float* __restrict__ cb, float* __restrict__ xc)
{
    int d   = blockIdx.x * 128 + threadIdx.x;  // 0..511
    int row = blockIdx.y;                      // b*Nseq + l
    int b   = row >> 9;
    int l   = row & (Nseq - 1);
    float v = cb[d];
#pragma unroll
    for (int j = 0; j < 4; j++) {
        int l2 = l + j - 3;
        if (l2 >= 0) v = fmaf(xiz[((long)(b * Nseq + l2)) * (2 * DIm) + d], cw[d * 4 + j], v);
    }
    xc[(long)row * DIm + d] = silu(v);
}

// -------- dt = softplus(dbc[:, :16] @ W_dt + b_dt) --------
__global__ void dt_kernel(const float* __restrict__ dbc, const float* __restrict__ Wd,
                          const float* __restrict__ bd, float* __restrict__ dt)
{
    int row = blockIdx.y;
    int d   = blockIdx.x * 128 + threadIdx.x;
    __shared__ float s[16];
    if (threadIdx.x < 16) s[threadIdx.x] = dbc[(long)row * 48 + threadIdx.x];
    __syncthreads();
    float v = bd[d];
#pragma unroll
    for (int r = 0; r < Rsz; r++) v = fmaf(s[r], Wd[r * DIm + d], v);
    dt[(long)row * DIm + d] = (v > 20.f) ? v : log1pf(__expf(v));
}

// -------- SSM scan: half-warp per (b,d) channel; lane%16 = state s --------
__global__ void scan_kernel(const float* __restrict__ dtb, const float* __restrict__ xc,
                            const float* __restrict__ dbc, const float* __restrict__ xiz,
                            const float* __restrict__ A_log, const float* __restrict__ Dsk,
                            float* __restrict__ y)
{
    int tid  = threadIdx.x;      // 256 = 8 warps = 16 scans
    int warp = tid >> 5, lane = tid & 31;
    int half = lane >> 4, s = lane & 15;
    int id = blockIdx.x * 16 + warp * 2 + half;   // [0, Bsz*DIm)
    int b  = id >> 9;            // / DIm
    int d  = id & (DIm - 1);

    float negA = -__expf(A_log[d * Ssz + s]);
    float Dp   = Dsk[d];
    float h    = 0.f;

    for (int l = 0; l < Nseq; l++) {
        long row = (long)b * Nseq + l;
        float dtv = dtb[row * DIm + d];
        float xcv = xc [row * DIm + d];
        float Bmv = dbc[row * 48 + Rsz + s];
        float Cmv = dbc[row * 48 + Rsz + Ssz + s];
        h = fmaf(__expf(dtv * negA), h, dtv * xcv * Bmv);
        float p = h * Cmv;
        p += __shfl_xor_sync(0xffffffffu, p, 1);
        p += __shfl_xor_sync(0xffffffffu, p, 2);
        p += __shfl_xor_sync(0xffffffffu, p, 4);
        p += __shfl_xor_sync(0xffffffffu, p, 8);
        if (s == 0) {
            float z = xiz[row * (2 * DIm) + DIm + d];
            y[row * DIm + d] = (p + xcv * Dp) * silu(z);
        }
    }
}

// -------- sup = softmax_row(relu(emb @ emb^T)) --------
__global__ void sup_kernel(const float* __restrict__ emb, float* __restrict__ sup)
{
    int n   = blockIdx.x;
    int tid = threadIdx.x;   // 256; each handles m = tid, tid+256
    __shared__ float en[16];
    __shared__ float red[8];
    __shared__ float smx, ssum;
    if (tid < Ee) en[tid] = emb[n * Ee + tid];
    __syncthreads();
    float v0 = 0.f, v1 = 0.f;
#pragma unroll
    for (int e = 0; e < Ee; e++) {
        float ee = en[e];
        v0 = fmaf(ee, emb[tid * Ee + e], v0);
        v1 = fmaf(ee, emb[(tid + 256) * Ee + e], v1);
    }
    float sc0 = fmaxf(v0, 0.f), sc1 = fmaxf(v1, 0.f);
    float mx = fmaxf(sc0, sc1);
#pragma unroll
    for (int o = 16; o > 0; o >>= 1) mx = fmaxf(mx, __shfl_xor_sync(0xffffffffu, mx, o));
    if ((tid & 31) == 0) red[tid >> 5] = mx;
    __syncthreads();
    if (tid == 0) {
        float v = red[0];
        for (int i = 1; i < 8; i++) v = fmaxf(v, red[i]);
        smx = v;
    }
    __syncthreads();
    float e0 = __expf(sc0 - smx), e1 = __expf(sc1 - smx);
    float sl = e0 + e1;
#pragma unroll
    for (int o = 16; o > 0; o >>= 1) sl += __shfl_xor_sync(0xffffffffu, sl, o);
    __syncthreads();
    if ((tid & 31) == 0) red[tid >> 5] = sl;
    __syncthreads();
    if (tid == 0) {
        float v = 0.f;
        for (int i = 0; i < 8; i++) v += red[i];
        ssum = v;
    }
    __syncthreads();
    float inv = 1.f / ssum;
    sup[n * Nseq + tid]       = e0 * inv;
    sup[n * Nseq + tid + 256] = e1 * inv;
}

// -------- Wn[n,k,d,o] = sum_e emb[n,e] * pool[e,k,d,o] --------
__global__ void wn_kernel(const float* __restrict__ pool, const float* __restrict__ emb,
                          float* __restrict__ wn)
{
    int kd = blockIdx.x;    // 0..767  (k*256 + d)
    int o  = threadIdx.x;   // 0..255
    float pe[Ee];
#pragma unroll
    for (int e = 0; e < Ee; e++) pe[e] = pool[((long)e * (Kc * Dd) + kd) * Dd + o];
    for (int n = 0; n < Nseq; n++) {
        float w = 0.f;
#pragma unroll
        for (int e = 0; e < Ee; e++) w = fmaf(__ldg(&emb[n * Ee + e]), pe[e], w);
        wn[((long)n * (Kc * Dd) + kd) * Dd + o] = w;
    }
}

// -------- x2[b,n,o] = sum_{k,d} xg[b,k,n,d]*Wn[n,k,d,o] + (emb@bias_pool)[n,o]
__global__ void x2_kernel(const float* __restrict__ x, const float* __restrict__ t1,
                          const float* __restrict__ t2, const float* __restrict__ wn,
                          const float* __restrict__ emb, const float* __restrict__ bpool,
                          float* __restrict__ x2)
{
    int n = blockIdx.x;
    int o = threadIdx.x;  // 256
    __shared__ float xs[Kc][Bsz][Dd];
    for (int b = 0; b < Bsz; b++) {
        long off = ((long)b * Nseq + n) * Dd + o;
        float xv = x[off];
        xs[0][b][o] = xv;
        xs[1][b][o] = t1[off];
        xs[2][b][o] = 2.f * t2[off] - xv;
    }
    __syncthreads();
    float acc[Bsz];
#pragma unroll
    for (int b = 0; b < Bsz; b++) acc[b] = 0.f;
    const float* wp = wn + (long)n * (Kc * Dd) * Dd;
    for (int kd = 0; kd < Kc * Dd; kd++) {
        float w = wp[(long)kd * Dd + o];
        int k = kd >> 8, d = kd & 255;
#pragma unroll
        for (int b = 0; b < Bsz; b++) acc[b] = fmaf(xs[k][b][d], w, acc[b]);
    }
    float bias = 0.f;
#pragma unroll
    for (int e = 0; e < Ee; e++) bias = fmaf(emb[n * Ee + e], bpool[e * Dd + o], bias);
    for (int b = 0; b < Bsz; b++)
        x2[((long)b * Nseq + n) * Dd + o] = acc[b] + bias;
}

// ---------------- host-side orchestration ----------------
static inline void gemm(const float* A, const float* B, const float* bias, float* C,
                        int M, int K, int N, int flipA, int flipC,
                        int accumulate, int act,
                        int batch = 1, long sA = 0, long sB = 0, long sC = 0)
{
    dim3 grid(N / 128, M / 128, batch);
    gemm128_kernel<<<grid, 256>>>(A, B, bias, C, K, N, flipA, flipC, Nseq,
                                  accumulate, act, sA, sB, sC);
}

extern "C" void kernel_launch(void* const* d_in, const int* in_sizes, int n_in,
                              void* d_out, int out_size)
{
    const float* input_  = (const float*)d_in[0];
    const float* ln1_g   = (const float*)d_in[1];
    const float* ln1_b   = (const float*)d_in[2];
    const float* ln2_g   = (const float*)d_in[3];
    const float* ln2_b   = (const float*)d_in[4];
    const float* W_in    = (const float*)d_in[5];
    const float* conv_w  = (const float*)d_in[6];
    const float* conv_b  = (const float*)d_in[7];
    const float* W_xproj = (const float*)d_in[8];
    const float* W_dt    = (const float*)d_in[9];
    const float* b_dt    = (const float*)d_in[10];
    const float* A_log   = (const float*)d_in[11];
    const float* D_skip  = (const float*)d_in[12];
    const float* W_out   = (const float*)d_in[13];
    const float* ffn_W1  = (const float*)d_in[14];
    const float* ffn_b1  = (const float*)d_in[15];
    const float* ffn_W2  = (const float*)d_in[16];
    const float* ffn_b2  = (const float*)d_in[17];
    const float* node_emb     = (const float*)d_in[18];
    const float* weights_pool = (const float*)d_in[19];
    const float* bias_pool    = (const float*)d_in[20];
    const float* W_proj  = (const float*)d_in[21];
    const float* b_proj  = (const float*)d_in[22];
    float* out = (float*)d_out;

    float *x_, *xn_, *xiz_, *xc_, *dbc_, *dt_, *y_, *t1_, *t2_, *sup_, *wn_, *x2_;
    cudaGetSymbolAddress((void**)&x_,   g_x);
    cudaGetSymbolAddress((void**)&xn_,  g_xn);
    cudaGetSymbolAddress((void**)&xiz_, g_xiz);
    cudaGetSymbolAddress((void**)&xc_,  g_xc);
    cudaGetSymbolAddress((void**)&dbc_, g_dbc);
    cudaGetSymbolAddress((void**)&dt_,  g_dt);
    cudaGetSymbolAddress((void**)&y_,   g_y);
    cudaGetSymbolAddress((void**)&t1_,  g_t1);
    cudaGetSymbolAddress((void**)&t2_,  g_t2);
    cudaGetSymbolAddress((void**)&sup_, g_sup);
    cudaGetSymbolAddress((void**)&wn_,  g_wn);
    cudaGetSymbolAddress((void**)&x2_,  g_x2);

    // x = input
    cudaMemcpyAsync(x_, input_, (size_t)ROWS * Dd * sizeof(float),
                    cudaMemcpyDeviceToDevice);

    for (int layer = 0; layer < 3; layer++) {
        ln_kernel<<<ROWS, Dd>>>(x_, ln1_g, ln1_b, xn_);

        for (int dir = 0; dir < 2; dir++) {
            const float* Wi = W_in    + (long)dir * Dd * 2 * DIm;
            const float* cw = conv_w  + (long)dir * DIm * 4;
            const float* cb = conv_b  + (long)dir * DIm;
            const float* Wx = W_xproj + (long)dir * DIm * (Rsz + 2 * Ssz);
            const float* Wd = W_dt    + (long)dir * Rsz * DIm;
            const float* bd = b_dt    + (long)dir * DIm;
            const float* Al = A_log   + (long)dir * DIm * Ssz;
            const float* Dp = D_skip  + (long)dir * DIm;
            const float* Wo = W_out   + (long)dir * DIm * Dd;

            // xiz = (dir ? flip(xn) : xn) @ Wi
            gemm(xn_, Wi, nullptr, xiz_, ROWS, Dd, 2 * DIm, dir, 0, 0, 0);
            // xc = silu(causal_conv(xi))
            conv_silu_kernel<<<dim3(DIm / 128, ROWS), 128>>>(xiz_, cw, cb, xc_);
            // dbc = xc @ Wx   (48 cols: dt_in | B | C)
            gemm_skinny_kernel<3><<<ROWS / 64, 256>>>(xc_, Wx, nullptr, dbc_, DIm);
            // dt = softplus(dbc[:, :16] @ Wd + bd)
            dt_kernel<<<dim3(DIm / 128, ROWS), 128>>>(dbc_, Wd, bd, dt_);
            // selective scan -> y
            scan_kernel<<<(Bsz * DIm) / 16, 256>>>(dt_, xc_, dbc_, xiz_, Al, Dp, y_);
            // x += (flip back if dir) y @ Wo
            gemm(y_, Wo, nullptr, x_, ROWS, DIm, Dd, 0, dir, 1, 0);
        }

        // FFN: x += silu(LN2(x) @ W1 + b1) @ W2 + b2
        ln_kernel<<<ROWS, Dd>>>(x_, ln2_g, ln2_b, xn_);
        gemm(xn_, ffn_W1, ffn_b1, xc_, ROWS, Dd, Hh, 0, 0, 0, 1);
        gemm(xc_, ffn_W2, ffn_b2, x_, ROWS, Hh, Dd, 0, 0, 1, 0);
    }

    // graph tail
    sup_kernel<<<Nseq, 256>>>(node_emb, sup_);
    gemm(sup_, x_,  nullptr, t1_, Nseq, Nseq, Dd, 0, 0, 0, 0,
         Bsz, 0, (long)Nseq * Dd, (long)Nseq * Dd);
    gemm(sup_, t1_, nullptr, t2_, Nseq, Nseq, Dd, 0, 0, 0, 0,
         Bsz, 0, (long)Nseq * Dd, (long)Nseq * Dd);
    wn_kernel<<<Kc * Dd, Dd>>>(weights_pool, node_emb, wn_);
    x2_kernel<<<Nseq, Dd>>>(x_, t1_, t2_, wn_, node_emb, bias_pool, x2_);
    // out = x2 @ W_proj + b_proj   (N=96)
    gemm_skinny_kernel<6><<<ROWS / 64, 256>>>(x2_, W_proj, b_proj, out, Dd);
}

// round 10
// speedup vs baseline: 1.8093x; 1.3046x over previous
#include <cuda_runtime.h>
#include <math.h>

#define Bsz  16
#define Nseq 512
#define Dd   256
#define DIm  512
#define Ssz  16
#define Rsz  16
#define Hh   512
#define Ee   10
#define Kc   3
#define Pp   96
#define ROWS (Bsz*Nseq)   /* 8192 */
#define DBCS 128          /* padded dbc row stride */

// ---------------- scratch (static device globals; no allocs) ----------------
__device__ float g_x  [ROWS*Dd];
__device__ float g_xn [ROWS*Dd];
__device__ float g_xiz[(size_t)ROWS*2*DIm];
__device__ float g_xc [(size_t)ROWS*DIm];
__device__ float g_dbc[(size_t)ROWS*DBCS];
__device__ float g_dt [(size_t)ROWS*DIm];
__device__ float g_y  [(size_t)ROWS*DIm];
__device__ float g_t1 [ROWS*Dd];
__device__ float g_t2 [ROWS*Dd];
__device__ float g_sup[Nseq*Nseq];
__device__ float g_wn [(size_t)Nseq*Kc*Dd*Dd];   // 403 MB
__device__ float g_x2 [ROWS*Dd];
__device__ float g_wxp[2*DIm*DBCS];   // padded W_xproj
__device__ float g_wpp[Dd*DBCS];      // padded W_proj
__device__ float g_bpp[DBCS];         // padded b_proj
__device__ float g_x2p[(size_t)ROWS*DBCS];

__device__ __forceinline__ float silu(float v) { return v / (1.f + __expf(-v)); }

// ---------------- packed f32x2 helpers ----------------
typedef unsigned long long u64;
__device__ __forceinline__ u64 pk2(float v) {
    u64 r; asm("mov.b64 %0, {%1, %1};" : "=l"(r) : "f"(v)); return r;
}
__device__ __forceinline__ u64 f2fma(u64 a, u64 b, u64 c) {
    u64 d; asm("fma.rn.f32x2 %0, %1, %2, %3;" : "=l"(d) : "l"(a), "l"(b), "l"(c)); return d;
}
__device__ __forceinline__ float2 up2(u64 v) {
    float2 f; asm("mov.b64 {%0, %1}, %2;" : "=f"(f.x), "=f"(f.y) : "l"(v)); return f;
}

// =================== 128x128x16 fp32 SGEMM, f32x2 FMA, double buffered ======
// Requires: M%128==0, N%128==0, K%16==0.
// C[=|+=] act(A@B + bias); optional per-period row flip on A reads / C writes.
__global__ __launch_bounds__(256, 2)
void gemm128_kernel(const float* __restrict__ A, const float* __restrict__ Bm,
                    const float* __restrict__ bias, float* __restrict__ C,
                    int Kd, int Nd,
                    int flipA, int flipC, int period,
                    int accumulate, int act,
                    long sA, long sB, long sC)
{
    A  += (long)blockIdx.z * sA;
    Bm += (long)blockIdx.z * sB;
    C  += (long)blockIdx.z * sC;

    __shared__ float As[2][16][128];
    __shared__ float Bs[2][16][128];

    const int t    = threadIdx.x;
    const int brow = blockIdx.y * 128;
    const int bcol = blockIdx.x * 128;

    const int a_r = t >> 1, a_c = (t & 1) * 8;     // A: 128 rows x 16 k, 2 float4/thread
    const int b_r = t >> 4, b_c = (t & 15) * 8;    // B: 16 k x 128 cols, 2 float4/thread
    const int ty  = t >> 4, tx  = t & 15;          // 16x16 threads, 8x8 frags

    int ar_g = brow + a_r;
    if (flipA) { int q = ar_g / period; ar_g = q * period + (period - 1 - (ar_g - q * period)); }
    const float* Aptr = A + (long)ar_g * Kd + a_c;
    const float* Bptr = Bm + (long)b_r * Nd + bcol + b_c;

    float4 a0, a1, b0, b1;
    a0 = *(const float4*)(Aptr);
    a1 = *(const float4*)(Aptr + 4);
    b0 = *(const float4*)(Bptr);
    b1 = *(const float4*)(Bptr + 4);
#pragma unroll
    for (int i = 0; i < 4; i++) {
        As[0][a_c + i][a_r]     = ((const float*)&a0)[i];
        As[0][a_c + 4 + i][a_r] = ((const float*)&a1)[i];
    }
    *(float4*)&Bs[0][b_r][b_c]     = b0;
    *(float4*)&Bs[0][b_r][b_c + 4] = b1;
    __syncthreads();

    u64 acc[8][4];
#pragma unroll
    for (int i = 0; i < 8; i++)
#pragma unroll
        for (int j = 0; j < 4; j++) acc[i][j] = 0ull;

    const int nk = Kd >> 4;
    int buf = 0;
    for (int kt = 0; kt < nk; kt++) {
        if (kt + 1 < nk) {
            const float* Ap2 = Aptr + (kt + 1) * 16;
            const float* Bp2 = Bptr + (long)(kt + 1) * 16 * Nd;
            a0 = *(const float4*)(Ap2);
            a1 = *(const float4*)(Ap2 + 4);
            b0 = *(const float4*)(Bp2);
            b1 = *(const float4*)(Bp2 + 4);
        }
#pragma unroll
        for (int kk = 0; kk < 16; kk++) {
            float4 af0 = *(const float4*)&As[buf][kk][ty * 8];
            float4 af1 = *(const float4*)&As[buf][kk][ty * 8 + 4];
            ulonglong2 bb0 = *(const ulonglong2*)&Bs[buf][kk][tx * 8];
            ulonglong2 bb1 = *(const ulonglong2*)&Bs[buf][kk][tx * 8 + 4];
            u64 bq[4] = { bb0.x, bb0.y, bb1.x, bb1.y };
            float av[8] = { af0.x, af0.y, af0.z, af0.w, af1.x, af1.y, af1.z, af1.w };
#pragma unroll
            for (int i = 0; i < 8; i++) {
                u64 ap = pk2(av[i]);
#pragma unroll
                for (int j = 0; j < 4; j++) acc[i][j] = f2fma(ap, bq[j], acc[i][j]);
            }
        }
        if (kt + 1 < nk) {
            int nb = buf ^ 1;
#pragma unroll
            for (int i = 0; i < 4; i++) {
                As[nb][a_c + i][a_r]     = ((const float*)&a0)[i];
                As[nb][a_c + 4 + i][a_r] = ((const float*)&a1)[i];
            }
            *(float4*)&Bs[nb][b_r][b_c]     = b0;
            *(float4*)&Bs[nb][b_r][b_c + 4] = b1;
            __syncthreads();
            buf = nb;
        }
    }

    // epilogue
#pragma unroll
    for (int i = 0; i < 8; i++) {
        int gr = brow + ty * 8 + i;
        int pr = gr;
        if (flipC) { int q = gr / period; pr = q * period + (period - 1 - (gr - q * period)); }
        float* crow = C + (long)pr * Nd + bcol + tx * 8;
        float2 p0 = up2(acc[i][0]), p1 = up2(acc[i][1]);
        float2 p2 = up2(acc[i][2]), p3 = up2(acc[i][3]);
        float4 va = make_float4(p0.x, p0.y, p1.x, p1.y);
        float4 vb = make_float4(p2.x, p2.y, p3.x, p3.y);
        if (bias) {
            float4 ba = *(const float4*)&bias[bcol + tx * 8];
            float4 bb = *(const float4*)&bias[bcol + tx * 8 + 4];
            va.x += ba.x; va.y += ba.y; va.z += ba.z; va.w += ba.w;
            vb.x += bb.x; vb.y += bb.y; vb.z += bb.z; vb.w += bb.w;
        }
        if (act == 1) {
            va.x = silu(va.x); va.y = silu(va.y); va.z = silu(va.z); va.w = silu(va.w);
            vb.x = silu(vb.x); vb.y = silu(vb.y); vb.z = silu(vb.z); vb.w = silu(vb.w);
        }
        if (accumulate) {
            float4 oa = *(const float4*)(crow);
            float4 ob = *(const float4*)(crow + 4);
            va.x += oa.x; va.y += oa.y; va.z += oa.z; va.w += oa.w;
            vb.x += ob.x; vb.y += ob.y; vb.z += ob.z; vb.w += ob.w;
        }
        *(float4*)(crow)     = va;
        *(float4*)(crow + 4) = vb;
    }
}

// ---------------- padding / unpadding helpers ----------------
__global__ void pad_wx_kernel(const float* __restrict__ Wx, float* __restrict__ wxp)
{
    int idx = blockIdx.x * 256 + threadIdx.x;       // 2*512*128
    int col = idx & 127;
    int row = (idx >> 7) & 511;
    int dir = idx >> 16;
    wxp[idx] = (col < 48) ? Wx[((long)dir * DIm + row) * 48 + col] : 0.f;
}

__global__ void pad_wp_kernel(const float* __restrict__ Wp, const float* __restrict__ bp,
                              float* __restrict__ wpp, float* __restrict__ bpp)
{
    int idx = blockIdx.x * 256 + threadIdx.x;       // 256*128
    int col = idx & 127, row = idx >> 7;
    wpp[idx] = (col < Pp) ? Wp[row * Pp + col] : 0.f;
    if (row == 0) bpp[col] = (col < Pp) ? bp[col] : 0.f;
}

__global__ void unpad_out_kernel(const float* __restrict__ x2p, float* __restrict__ out)
{
    int idx = blockIdx.x * 256 + threadIdx.x;       // ROWS*96
    int col = idx % Pp, row = idx / Pp;
    out[idx] = x2p[(long)row * DBCS + col];
}

// ---------------- layernorm over D=256 (one block per row) ----------------
__global__ void ln_kernel(const float* __restrict__ x, const float* __restrict__ g,
                          const float* __restrict__ b, float* __restrict__ out)
{
    int row = blockIdx.x;
    int d   = threadIdx.x;    // 256 == Dd
    float v = x[(long)row * Dd + d];
    float s1 = v, s2 = v * v;
#pragma unroll
    for (int o = 16; o > 0; o >>= 1) {
        s1 += __shfl_xor_sync(0xffffffffu, s1, o);
        s2 += __shfl_xor_sync(0xffffffffu, s2, o);
    }
    __shared__ float a1[8], a2[8];
    __shared__ float mean, rstd;
    if ((d & 31) == 0) { a1[d >> 5] = s1; a2[d >> 5] = s2; }
    __syncthreads();
    if (d == 0) {
        float t1 = 0.f, t2 = 0.f;
        for (int i = 0; i < 8; i++) { t1 += a1[i]; t2 += a2[i]; }
        float m = t1 / (float)Dd;
        float var = t2 / (float)Dd - m * m;
        mean = m;
        rstd = rsqrtf(var + 1e-5f);
    }
    __syncthreads();
    out[(long)row * Dd + d] = (v - mean) * rstd * g[d] + b[d];
}

// -------- causal depthwise conv (width 4) + silu ----------
__global__ void conv_silu_kernel(const float* __restrict__ xiz, const float* __restrict__ cw,
                                 const float* __restrict__ cb, float* __restrict__ xc)
{
    int d   = blockIdx.x * 128 + threadIdx.x;  // 0..511
    int row = blockIdx.y;                      // b*Nseq + l
    int b   = row >> 9;
    int l   = row & (Nseq - 1);
    float v = cb[d];
#pragma unroll
    for (int j = 0; j < 4; j++) {
        int l2 = l + j - 3;
        if (l2 >= 0) v = fmaf(xiz[((long)(b * Nseq + l2)) * (2 * DIm) + d], cw[d * 4 + j], v);
    }
    xc[(long)row * DIm + d] = silu(v);
}

// -------- dt = softplus(dbc[:, :16] @ W_dt + b_dt) --------
__global__ void dt_kernel(const float* __restrict__ dbc, const float* __restrict__ Wd,
                          const float* __restrict__ bd, float* __restrict__ dt)
{
    int row = blockIdx.y;
    int d   = blockIdx.x * 128 + threadIdx.x;
    __shared__ float s[16];
    if (threadIdx.x < 16) s[threadIdx.x] = dbc[(long)row * DBCS + threadIdx.x];
    __syncthreads();
    float v = bd[d];
#pragma unroll
    for (int r = 0; r < Rsz; r++) v = fmaf(s[r], Wd[r * DIm + d], v);
    dt[(long)row * DIm + d] = (v > 20.f) ? v : log1pf(__expf(v));
}

// ======== SSM scan v2: 4 lanes/channel x 4 states, smem-staged chunks ========
#define SCH 64   // channels per block (same b, consecutive d)
#define SCT 32   // timesteps per smem chunk
__global__ __launch_bounds__(256)
void scan_kernel(const float* __restrict__ dtb, const float* __restrict__ xc,
                 const float* __restrict__ dbc, const float* __restrict__ xiz,
                 const float* __restrict__ A_log, const float* __restrict__ Dsk,
                 float* __restrict__ y)
{
    int t    = threadIdx.x;
    int lane = t & 31;
    int warp = t >> 5;
    int cl   = warp * 8 + (lane >> 2);    // local channel 0..63
    int sub  = lane & 3;                  // state group
    int c0   = blockIdx.x * SCH;          // global channel base (multiple of 64)
    int b    = c0 >> 9;                   // same b for whole block (DIm=512)
    int d0   = c0 & (DIm - 1);
    int d    = d0 + cl;

    float negA[4], h[4];
#pragma unroll
    for (int k = 0; k < 4; k++) {
        negA[k] = -__expf(A_log[d * Ssz + sub * 4 + k]);
        h[k] = 0.f;
    }
    float Dp = Dsk[d];

    __shared__ float dtS[SCT][SCH];
    __shared__ float xcS[SCT][SCH];
    __shared__ float zS [SCT][SCH];
    __shared__ float bcS[SCT][32];   // [B(16) | C(16)] per step

    for (int l0 = 0; l0 < Nseq; l0 += SCT) {
        __syncthreads();
        for (int i = t; i < SCT * SCH; i += 256) {
            int r = i >> 6, c = i & 63;
            long row = (long)b * Nseq + l0 + r;
            dtS[r][c] = dtb[row * DIm + d0 + c];
            xcS[r][c] = xc [row * DIm + d0 + c];
            zS [r][c] = xiz[row * (2 * DIm) + DIm + d0 + c];
        }
        for (int i = t; i < SCT * 32; i += 256) {
            int r = i >> 5, c = i & 31;
            bcS[r][c] = dbc[((long)b * Nseq + l0 + r) * DBCS + 16 + c];
        }
        __syncthreads();
#pragma unroll 4
        for (int l = 0; l < SCT; l++) {
            float dtv = dtS[l][cl];
            float xcv = xcS[l][cl];
            float4 Bv = *(const float4*)&bcS[l][sub * 4];
            float4 Cv = *(const float4*)&bcS[l][16 + sub * 4];
            float dtx = dtv * xcv;
            h[0] = fmaf(__expf(dtv * negA[0]), h[0], dtx * Bv.x);
            h[1] = fmaf(__expf(dtv * negA[1]), h[1], dtx * Bv.y);
            h[2] = fmaf(__expf(dtv * negA[2]), h[2], dtx * Bv.z);
            h[3] = fmaf(__expf(dtv * negA[3]), h[3], dtx * Bv.w);
            float p = h[0] * Cv.x;
            p = fmaf(h[1], Cv.y, p);
            p = fmaf(h[2], Cv.z, p);
            p = fmaf(h[3], Cv.w, p);
            p += __shfl_xor_sync(0xffffffffu, p, 1);
            p += __shfl_xor_sync(0xffffffffu, p, 2);
            if (sub == 0) {
                float z = zS[l][cl];
                y[((long)b * Nseq + l0 + l) * DIm + d] = (p + xcv * Dp) * silu(z);
            }
        }
    }
}

// -------- sup = softmax_row(relu(emb @ emb^T)) --------
__global__ void sup_kernel(const float* __restrict__ emb, float* __restrict__ sup)
{
    int n   = blockIdx.x;
    int tid = threadIdx.x;   // 256; each handles m = tid, tid+256
    __shared__ float en[16];
    __shared__ float red[8];
    __shared__ float smx, ssum;
    if (tid < Ee) en[tid] = emb[n * Ee + tid];
    __syncthreads();
    float v0 = 0.f, v1 = 0.f;
#pragma unroll
    for (int e = 0; e < Ee; e++) {
        float ee = en[e];
        v0 = fmaf(ee, emb[tid * Ee + e], v0);
        v1 = fmaf(ee, emb[(tid + 256) * Ee + e], v1);
    }
    float sc0 = fmaxf(v0, 0.f), sc1 = fmaxf(v1, 0.f);
    float mx = fmaxf(sc0, sc1);
#pragma unroll
    for (int o = 16; o > 0; o >>= 1) mx = fmaxf(mx, __shfl_xor_sync(0xffffffffu, mx, o));
    if ((tid & 31) == 0) red[tid >> 5] = mx;
    __syncthreads();
    if (tid == 0) {
        float v = red[0];
        for (int i = 1; i < 8; i++) v = fmaxf(v, red[i]);
        smx = v;
    }
    __syncthreads();
    float e0 = __expf(sc0 - smx), e1 = __expf(sc1 - smx);
    float sl = e0 + e1;
#pragma unroll
    for (int o = 16; o > 0; o >>= 1) sl += __shfl_xor_sync(0xffffffffu, sl, o);
    __syncthreads();
    if ((tid & 31) == 0) red[tid >> 5] = sl;
    __syncthreads();
    if (tid == 0) {
        float v = 0.f;
        for (int i = 0; i < 8; i++) v += red[i];
        ssum = v;
    }
    __syncthreads();
    float inv = 1.f / ssum;
    sup[n * Nseq + tid]       = e0 * inv;
    sup[n * Nseq + tid + 256] = e1 * inv;
}

// -------- Wn[n,k,d,o] = sum_e emb[n,e] * pool[e,k,d,o] --------
__global__ void wn_kernel(const float* __restrict__ pool, const float* __restrict__ emb,
                          float* __restrict__ wn)
{
    int kd = blockIdx.x;    // 0..767  (k*256 + d)
    int o  = threadIdx.x;   // 0..255
    float pe[Ee];
#pragma unroll
    for (int e = 0; e < Ee; e++) pe[e] = pool[((long)e * (Kc * Dd) + kd) * Dd + o];
    for (int n = 0; n < Nseq; n++) {
        float w = 0.f;
#pragma unroll
        for (int e = 0; e < Ee; e++) w = fmaf(__ldg(&emb[n * Ee + e]), pe[e], w);
        wn[((long)n * (Kc * Dd) + kd) * Dd + o] = w;
    }
}

// -------- x2[b,n,o] = sum_{k,d} xg[b,k,n,d]*Wn[n,k,d,o] + (emb@bias_pool)[n,o]
__global__ void x2_kernel(const float* __restrict__ x, const float* __restrict__ t1,
                          const float* __restrict__ t2, const float* __restrict__ wn,
                          const float* __restrict__ emb, const float* __restrict__ bpool,
                          float* __restrict__ x2)
{
    int n = blockIdx.x;
    int o = threadIdx.x;  // 256
    __shared__ float xs[Kc][Bsz][Dd];
    for (int b = 0; b < Bsz; b++) {
        long off = ((long)b * Nseq + n) * Dd + o;
        float xv = x[off];
        xs[0][b][o] = xv;
        xs[1][b][o] = t1[off];
        xs[2][b][o] = 2.f * t2[off] - xv;
    }
    __syncthreads();
    float acc[Bsz];
#pragma unroll
    for (int b = 0; b < Bsz; b++) acc[b] = 0.f;
    const float* wp = wn + (long)n * (Kc * Dd) * Dd;
    for (int kd = 0; kd < Kc * Dd; kd++) {
        float w = wp[(long)kd * Dd + o];
        int k = kd >> 8, d = kd & 255;
#pragma unroll
        for (int b = 0; b < Bsz; b++) acc[b] = fmaf(xs[k][b][d], w, acc[b]);
    }
    float bias = 0.f;
#pragma unroll
    for (int e = 0; e < Ee; e++) bias = fmaf(emb[n * Ee + e], bpool[e * Dd + o], bias);
    for (int b = 0; b < Bsz; b++)
        x2[((long)b * Nseq + n) * Dd + o] = acc[b] + bias;
}

// ---------------- host-side orchestration ----------------
static inline void gemm(const float* A, const float* B, const float* bias, float* C,
                        int M, int K, int N, int flipA, int flipC,
                        int accumulate, int act,
                        int batch = 1, long sA = 0, long sB = 0, long sC = 0)
{
    dim3 grid(N / 128, M / 128, batch);
    gemm128_kernel<<<grid, 256>>>(A, B, bias, C, K, N, flipA, flipC, Nseq,
                                  accumulate, act, sA, sB, sC);
}

extern "C" void kernel_launch(void* const* d_in, const int* in_sizes, int n_in,
                              void* d_out, int out_size)
{
    const float* input_  = (const float*)d_in[0];
    const float* ln1_g   = (const float*)d_in[1];
    const float* ln1_b   = (const float*)d_in[2];
    const float* ln2_g   = (const float*)d_in[3];
    const float* ln2_b   = (const float*)d_in[4];
    const float* W_in    = (const float*)d_in[5];
    const float* conv_w  = (const float*)d_in[6];
    const float* conv_b  = (const float*)d_in[7];
    const float* W_xproj = (const float*)d_in[8];
    const float* W_dt    = (const float*)d_in[9];
    const float* b_dt    = (const float*)d_in[10];
    const float* A_log   = (const float*)d_in[11];
    const float* D_skip  = (const float*)d_in[12];
    const float* W_out   = (const float*)d_in[13];
    const float* ffn_W1  = (const float*)d_in[14];
    const float* ffn_b1  = (const float*)d_in[15];
    const float* ffn_W2  = (const float*)d_in[16];
    const float* ffn_b2  = (const float*)d_in[17];
    const float* node_emb     = (const float*)d_in[18];
    const float* weights_pool = (const float*)d_in[19];
    const float* bias_pool    = (const float*)d_in[20];
    const float* W_proj  = (const float*)d_in[21];
    const float* b_proj  = (const float*)d_in[22];
    float* out = (float*)d_out;

    float *x_, *xn_, *xiz_, *xc_, *dbc_, *dt_, *y_, *t1_, *t2_, *sup_, *wn_, *x2_;
    float *wxp_, *wpp_, *bpp_, *x2p_;
    cudaGetSymbolAddress((void**)&x_,   g_x);
    cudaGetSymbolAddress((void**)&xn_,  g_xn);
    cudaGetSymbolAddress((void**)&xiz_, g_xiz);
    cudaGetSymbolAddress((void**)&xc_,  g_xc);
    cudaGetSymbolAddress((void**)&dbc_, g_dbc);
    cudaGetSymbolAddress((void**)&dt_,  g_dt);
    cudaGetSymbolAddress((void**)&y_,   g_y);
    cudaGetSymbolAddress((void**)&t1_,  g_t1);
    cudaGetSymbolAddress((void**)&t2_,  g_t2);
    cudaGetSymbolAddress((void**)&sup_, g_sup);
    cudaGetSymbolAddress((void**)&wn_,  g_wn);
    cudaGetSymbolAddress((void**)&x2_,  g_x2);
    cudaGetSymbolAddress((void**)&wxp_, g_wxp);
    cudaGetSymbolAddress((void**)&wpp_, g_wpp);
    cudaGetSymbolAddress((void**)&bpp_, g_bpp);
    cudaGetSymbolAddress((void**)&x2p_, g_x2p);

    // x = input; pad weights
    cudaMemcpyAsync(x_, input_, (size_t)ROWS * Dd * sizeof(float),
                    cudaMemcpyDeviceToDevice);
    pad_wx_kernel<<<(2 * DIm * DBCS) / 256, 256>>>(W_xproj, wxp_);
    pad_wp_kernel<<<(Dd * DBCS) / 256, 256>>>(W_proj, b_proj, wpp_, bpp_);

    for (int layer = 0; layer < 3; layer++) {
        ln_kernel<<<ROWS, Dd>>>(x_, ln1_g, ln1_b, xn_);

        for (int dir = 0; dir < 2; dir++) {
            const float* Wi = W_in    + (long)dir * Dd * 2 * DIm;
            const float* cw = conv_w  + (long)dir * DIm * 4;
            const float* cb = conv_b  + (long)dir * DIm;
            const float* Wd = W_dt    + (long)dir * Rsz * DIm;
            const float* bd = b_dt    + (long)dir * DIm;
            const float* Al = A_log   + (long)dir * DIm * Ssz;
            const float* Dp = D_skip  + (long)dir * DIm;
            const float* Wo = W_out   + (long)dir * DIm * Dd;

            // xiz = (dir ? flip(xn) : xn) @ Wi
            gemm(xn_, Wi, nullptr, xiz_, ROWS, Dd, 2 * DIm, dir, 0, 0, 0);
            // xc = silu(causal_conv(xi))
            conv_silu_kernel<<<dim3(DIm / 128, ROWS), 128>>>(xiz_, cw, cb, xc_);
            // dbc = xc @ Wxp  (padded to 128 cols)
            gemm(xc_, wxp_ + (long)dir * DIm * DBCS, nullptr, dbc_, ROWS, DIm, DBCS, 0, 0, 0, 0);
            // dt = softplus(dbc[:, :16] @ Wd + bd)
            dt_kernel<<<dim3(DIm / 128, ROWS), 128>>>(dbc_, Wd, bd, dt_);
            // selective scan -> y
            scan_kernel<<<(Bsz * DIm) / SCH, 256>>>(dt_, xc_, dbc_, xiz_, Al, Dp, y_);
            // x += (flip back if dir) y @ Wo
            gemm(y_, Wo, nullptr, x_, ROWS, DIm, Dd, 0, dir, 1, 0);
        }

        // FFN: x += silu(LN2(x) @ W1 + b1) @ W2 + b2
        ln_kernel<<<ROWS, Dd>>>(x_, ln2_g, ln2_b, xn_);
        gemm(xn_, ffn_W1, ffn_b1, xc_, ROWS, Dd, Hh, 0, 0, 0, 1);
        gemm(xc_, ffn_W2, ffn_b2, x_, ROWS, Hh, Dd, 0, 0, 1, 0);
    }

    // graph tail
    sup_kernel<<<Nseq, 256>>>(node_emb, sup_);
    gemm(sup_, x_,  nullptr, t1_, Nseq, Nseq, Dd, 0, 0, 0, 0,
         Bsz, 0, (long)Nseq * Dd, (long)Nseq * Dd);
    gemm(sup_, t1_, nullptr, t2_, Nseq, Nseq, Dd, 0, 0, 0, 0,
         Bsz, 0, (long)Nseq * Dd, (long)Nseq * Dd);
    wn_kernel<<<Kc * Dd, Dd>>>(weights_pool, node_emb, wn_);
    x2_kernel<<<Nseq, Dd>>>(x_, t1_, t2_, wn_, node_emb, bias_pool, x2_);
    // out = x2 @ W_proj + b_proj (padded to 128, then unpad)
    gemm(x2_, wpp_, bpp_, x2p_, ROWS, Dd, DBCS, 0, 0, 0, 0);
    unpad_out_kernel<<<(ROWS * Pp) / 256, 256>>>(x2p_, out);
}